// round 7
// baseline (speedup 1.0000x reference)
#include <cuda_runtime.h>
#include <cuda_bf16.h>
#include <math.h>
#include <stdint.h>

#define B_ 32
#define T_ 2048
#define D_ 512
#define U_ 512
#define MT 65536            // B_*T_

// ---- score GEMM tiling ----
#define TILE_M 128
#define TILE_N 128
#define KC 32               // K elems per pipeline chunk
#define NCHUNK 16           // 512/32
#define PITCH 80            // 64B data + 16B pad -> conflict-free ldmatrix
#define A_H 0
#define A_L 10240
#define BT_H 20480
#define BT_L 30720
#define STAGE 40960
#define SMEM_TOTAL (2*STAGE + 1024)   // 82944 B -> 2 CTAs/SM

// ---- scratch (device globals: allocation-free) ----
__device__ float g_score[MT];
__device__ float g_pq[B_ * U_];
__device__ __nv_bfloat16 g_vh[(size_t)MT * D_];
__device__ __nv_bfloat16 g_vl[(size_t)MT * D_];
__device__ __nv_bfloat16 g_w1h[U_ * D_];   // [n][k] transposed, K-major
__device__ __nv_bfloat16 g_w1l[U_ * D_];

// ---------------------------------------------------------------------------
// PTX helpers — baseline (non-"a") features only: mma.sync / ldmatrix / cp.async
// ---------------------------------------------------------------------------
__device__ __forceinline__ uint32_t smem_u32(const void* p) {
    uint32_t a;
    asm("{ .reg .u64 t; cvta.to.shared.u64 t, %1; cvt.u32.u64 %0, t; }" : "=r"(a) : "l"(p));
    return a;
}
__device__ __forceinline__ void cp16(uint32_t dst, const void* src) {
    asm volatile("cp.async.cg.shared.global [%0], [%1], 16;" :: "r"(dst), "l"(src));
}
__device__ __forceinline__ void ldm4(uint32_t* r, uint32_t addr) {
    asm volatile("ldmatrix.sync.aligned.m8n8.x4.shared.b16 {%0,%1,%2,%3}, [%4];"
                 : "=r"(r[0]), "=r"(r[1]), "=r"(r[2]), "=r"(r[3]) : "r"(addr));
}
__device__ __forceinline__ void mma_bf16(float* d, const uint32_t* a,
                                         uint32_t b0, uint32_t b1) {
    asm volatile(
        "mma.sync.aligned.m16n8k16.row.col.f32.bf16.bf16.f32 "
        "{%0,%1,%2,%3}, {%4,%5,%6,%7}, {%8,%9}, {%0,%1,%2,%3};"
        : "+f"(d[0]), "+f"(d[1]), "+f"(d[2]), "+f"(d[3])
        : "r"(a[0]), "r"(a[1]), "r"(a[2]), "r"(a[3]), "r"(b0), "r"(b1));
}

// ---------------------------------------------------------------------------
// values fp32 -> bf16 hi + lo residual
// ---------------------------------------------------------------------------
__global__ void convert_values_kernel(const float* __restrict__ v) {
    const float4* v4 = (const float4*)v;
    __nv_bfloat162* vh2 = (__nv_bfloat162*)g_vh;
    __nv_bfloat162* vl2 = (__nv_bfloat162*)g_vl;
    size_t n4 = (size_t)MT * D_ / 4;
    for (size_t i = (size_t)blockIdx.x * blockDim.x + threadIdx.x; i < n4;
         i += (size_t)gridDim.x * blockDim.x) {
        float4 x = v4[i];
        __nv_bfloat16 hx = __float2bfloat16(x.x), hy = __float2bfloat16(x.y);
        __nv_bfloat16 hz = __float2bfloat16(x.z), hw = __float2bfloat16(x.w);
        __nv_bfloat162 h0, h1, l0, l1;
        h0.x = hx; h0.y = hy; h1.x = hz; h1.y = hw;
        l0.x = __float2bfloat16(x.x - __bfloat162float(hx));
        l0.y = __float2bfloat16(x.y - __bfloat162float(hy));
        l1.x = __float2bfloat16(x.z - __bfloat162float(hz));
        l1.y = __float2bfloat16(x.w - __bfloat162float(hw));
        vh2[2*i] = h0; vh2[2*i+1] = h1;
        vl2[2*i] = l0; vl2[2*i+1] = l1;
    }
}

// W1 [K][N] -> transposed bf16 hi/lo [N][K]
__global__ void convert_w1_kernel(const float* __restrict__ W1) {
    __shared__ float t[32][33];
    int k0 = blockIdx.y * 32, n0 = blockIdx.x * 32;
    int tx = threadIdx.x & 31, ty = threadIdx.x >> 5;
    for (int r = ty; r < 32; r += 8) t[r][tx] = W1[(k0 + r) * U_ + n0 + tx];
    __syncthreads();
    for (int r = ty; r < 32; r += 8) {
        float x = t[tx][r];
        __nv_bfloat16 h = __float2bfloat16(x);
        g_w1h[(size_t)(n0 + r) * D_ + k0 + tx] = h;
        g_w1l[(size_t)(n0 + r) * D_ + k0 + tx] =
            __float2bfloat16(x - __bfloat162float(h));
    }
}

// ---------------------------------------------------------------------------
// proj_q + bias fold; also zeroes g_score (atomicAdd target)
// ---------------------------------------------------------------------------
__global__ void pq_kernel(const float* __restrict__ query,
                          const float* __restrict__ W2,
                          const float* __restrict__ W1b,
                          const float* __restrict__ W2b) {
    __shared__ float qs[D_];
    int b = blockIdx.x, u = threadIdx.x;
    qs[u] = query[b * D_ + u];
    for (int i = b * 512 + u; i < MT; i += B_ * 512) g_score[i] = 0.f;
    __syncthreads();
    float acc = 0.f;
#pragma unroll 8
    for (int d = 0; d < D_; d++) acc = fmaf(qs[d], W2[d * U_ + u], acc);
    g_pq[b * U_ + u] = acc + W1b[u] + W2b[u];
}

// ---------------------------------------------------------------------------
// Score GEMM via mma.sync bf16x3 + fused tanh/Vw epilogue
// grid: 2048 = 512 m-tiles x 4 n-slices; 256 threads (8 warps, 64x32 each)
// 2 CTAs/SM; dependency-free MMA passes (16 independent MMAs per pass)
// ---------------------------------------------------------------------------
extern __shared__ char smem_raw[];

__global__ __launch_bounds__(256, 2)
void score_kernel(const float* __restrict__ Vw) {
    const int tid  = threadIdx.x;
    const int lane = tid & 31;
    const int mtile = blockIdx.x >> 2;
    const int nq    = blockIdx.x & 3;
    const int row0  = mtile * TILE_M;
    const int b     = row0 >> 11;          // T_=2048
    const int n0    = nq * TILE_N;
    const int wid   = tid >> 5;
    const int m_w   = (wid >> 2) * 64;
    const int n_w   = (wid & 3) * 32;

    uint32_t sb = smem_u32(smem_raw);
    float* pqs = (float*)(smem_raw + 2 * STAGE);
    float* vws = pqs + 128;
    if (tid < 128) {
        pqs[tid] = g_pq[b * U_ + n0 + tid];
        vws[tid] = Vw[n0 + tid];
    }

    // ldmatrix per-lane address components
    const int rowA = lane & 15;
    const int colA = (lane >> 4) * 16;                       // bytes (8 bf16)
    const int rowB = (lane & 7) + ((lane >> 3) & 1) * 8;
    const int colB = (lane >> 4) * 16;

    float acc[4][4][4];
#pragma unroll
    for (int i = 0; i < 4; i++)
#pragma unroll
        for (int j = 0; j < 4; j++)
#pragma unroll
            for (int r = 0; r < 4; r++) acc[i][j][r] = 0.f;

    const __nv_bfloat16* Agh = g_vh  + (size_t)row0 * D_;
    const __nv_bfloat16* Agl = g_vl  + (size_t)row0 * D_;
    const __nv_bfloat16* Bgh = g_w1h + (size_t)n0   * D_;
    const __nv_bfloat16* Bgl = g_w1l + (size_t)n0   * D_;

    // loader indices: 512 granules (16B) per buffer, 2 iters x 256 threads
    const int lrow0 = tid >> 2;            // rows 0..63
    const int lcc   = (tid & 3) * 16;      // byte col within 64B row
    const int scc   = (tid & 3) * 8;       // elem col

#define LOAD_CHUNK(c, s)                                                     \
    do {                                                                     \
        uint32_t st = sb + (s) * STAGE;                                      \
        int k0 = (c) * KC;                                                   \
        _Pragma("unroll")                                                    \
        for (int i = 0; i < 2; i++) {                                        \
            int row = lrow0 + (i << 6);                                      \
            uint32_t doff = row * PITCH + lcc;                               \
            size_t soff = (size_t)row * D_ + k0 + scc;                       \
            cp16(st + A_H  + doff, Agh + soff);                              \
            cp16(st + A_L  + doff, Agl + soff);                              \
            cp16(st + BT_H + doff, Bgh + soff);                              \
            cp16(st + BT_L + doff, Bgl + soff);                              \
        }                                                                    \
        asm volatile("cp.async.commit_group;" ::: "memory");                 \
    } while (0)

    LOAD_CHUNK(0, 0);

    const uint32_t a_h0 = sb + A_H  + (m_w + rowA) * PITCH + colA;
    const uint32_t a_l0 = sb + A_L  + (m_w + rowA) * PITCH + colA;
    const uint32_t b_h0 = sb + BT_H + (n_w + rowB) * PITCH + colB;
    const uint32_t b_l0 = sb + BT_L + (n_w + rowB) * PITCH + colB;

    for (int c = 0; c < NCHUNK; c++) {
        int s = c & 1;
        if (c + 1 < NCHUNK) {
            LOAD_CHUNK(c + 1, s ^ 1);
            asm volatile("cp.async.wait_group 1;" ::: "memory");
        } else {
            asm volatile("cp.async.wait_group 0;" ::: "memory");
        }
        __syncthreads();

        const uint32_t so = s * STAGE;
#pragma unroll
        for (int k = 0; k < 2; k++) {                 // 2 x k16 per 32-chunk
            const uint32_t ko = k * 32;

            // ---- pass 1: Ah * Bh (16 independent MMAs) ----
            uint32_t ah[4][4], bh[2][4];
#pragma unroll
            for (int i = 0; i < 4; i++)
                ldm4(ah[i], a_h0 + so + i * 16 * PITCH + ko);
#pragma unroll
            for (int jj = 0; jj < 2; jj++)
                ldm4(bh[jj], b_h0 + so + jj * 16 * PITCH + ko);
#pragma unroll
            for (int i = 0; i < 4; i++)
#pragma unroll
                for (int j = 0; j < 4; j++)
                    mma_bf16(acc[i][j], ah[i],
                             bh[j >> 1][j & 1], bh[j >> 1][2 + (j & 1)]);

            // ---- pass 2: Ah * Bl ----
            uint32_t bl[2][4];
#pragma unroll
            for (int jj = 0; jj < 2; jj++)
                ldm4(bl[jj], b_l0 + so + jj * 16 * PITCH + ko);
#pragma unroll
            for (int i = 0; i < 4; i++)
#pragma unroll
                for (int j = 0; j < 4; j++)
                    mma_bf16(acc[i][j], ah[i],
                             bl[j >> 1][j & 1], bl[j >> 1][2 + (j & 1)]);

            // ---- pass 3: Al * Bh ----
            uint32_t al[4][4];
#pragma unroll
            for (int i = 0; i < 4; i++)
                ldm4(al[i], a_l0 + so + i * 16 * PITCH + ko);
#pragma unroll
            for (int i = 0; i < 4; i++)
#pragma unroll
                for (int j = 0; j < 4; j++)
                    mma_bf16(acc[i][j], al[i],
                             bh[j >> 1][j & 1], bh[j >> 1][2 + (j & 1)]);
        }
        __syncthreads();
    }

    // Epilogue: tanh(acc+pq)*Vw, reduce over n (regs -> shfl -> atomicAdd)
    float part[4][2];
#pragma unroll
    for (int i = 0; i < 4; i++) { part[i][0] = 0.f; part[i][1] = 0.f; }
#pragma unroll
    for (int i = 0; i < 4; i++)
#pragma unroll
        for (int j = 0; j < 4; j++)
#pragma unroll
            for (int r = 0; r < 4; r++) {
                int nl = n_w + j * 8 + 2 * (lane & 3) + (r & 1);
                float x = acc[i][j][r] + pqs[nl];
                part[i][r >> 1] += tanhf(x) * vws[nl];
            }
#pragma unroll
    for (int i = 0; i < 4; i++)
#pragma unroll
        for (int h = 0; h < 2; h++) {
            float v = part[i][h];
            v += __shfl_xor_sync(0xffffffffu, v, 1);
            v += __shfl_xor_sync(0xffffffffu, v, 2);
            if ((lane & 3) == 0)
                atomicAdd(&g_score[row0 + m_w + i * 16 + h * 8 + (lane >> 2)], v);
        }
}

// ---------------------------------------------------------------------------
// Softmax over T per batch; weights -> d_out[B*D ..)
// ---------------------------------------------------------------------------
__global__ void softmax_kernel(float* __restrict__ out) {
    __shared__ float sm[256];
    int b = blockIdx.x, tid = threadIdx.x;
    const float* sc = g_score + b * T_;
    float m = -1e30f;
    for (int t = tid; t < T_; t += 256) m = fmaxf(m, sc[t]);
    sm[tid] = m; __syncthreads();
    for (int s = 128; s > 0; s >>= 1) {
        if (tid < s) sm[tid] = fmaxf(sm[tid], sm[tid + s]);
        __syncthreads();
    }
    float mx = sm[0]; __syncthreads();
    float sum = 0.f;
    for (int t = tid; t < T_; t += 256) sum += __expf(sc[t] - mx);
    sm[tid] = sum; __syncthreads();
    for (int s = 128; s > 0; s >>= 1) {
        if (tid < s) sm[tid] += sm[tid + s];
        __syncthreads();
    }
    float inv = 1.f / sm[0];
    float* w = out + B_ * D_ + b * T_;
    for (int t = tid; t < T_; t += 256) w[t] = __expf(sc[t] - mx) * inv;
}

// ---------------------------------------------------------------------------
// context[b,d] = sum_t w[b,t] * values[b,t,d]
// ---------------------------------------------------------------------------
__global__ void context_kernel(const float* __restrict__ values,
                               float* __restrict__ out) {
    int b = blockIdx.y;
    int t0 = blockIdx.x * 128;
    int d4 = threadIdx.x & 127;
    int th = threadIdx.x >> 7;
    const float* w = out + B_ * D_ + b * T_ + t0;
    const float4* v = (const float4*)(values + ((size_t)b * T_ + t0) * D_) + d4;
    float4 acc = make_float4(0.f, 0.f, 0.f, 0.f);
#pragma unroll 8
    for (int t = th; t < 128; t += 2) {
        float wt = w[t];
        float4 x = v[(size_t)t * 128];
        acc.x = fmaf(wt, x.x, acc.x);
        acc.y = fmaf(wt, x.y, acc.y);
        acc.z = fmaf(wt, x.z, acc.z);
        acc.w = fmaf(wt, x.w, acc.w);
    }
    float* o = out + b * D_ + d4 * 4;
    atomicAdd(o + 0, acc.x);
    atomicAdd(o + 1, acc.y);
    atomicAdd(o + 2, acc.z);
    atomicAdd(o + 3, acc.w);
}

// ---------------------------------------------------------------------------
extern "C" void kernel_launch(void* const* d_in, const int* in_sizes, int n_in,
                              void* d_out, int out_size) {
    const float* values = (const float*)d_in[0];
    const float* query  = (const float*)d_in[1];
    const float* W1w    = (const float*)d_in[2];
    const float* W1b    = (const float*)d_in[3];
    const float* W2w    = (const float*)d_in[4];
    const float* W2b    = (const float*)d_in[5];
    const float* Vw     = (const float*)d_in[6];
    // d_in[7] (V_b) unused: softmax is shift-invariant.
    float* out = (float*)d_out;

    cudaFuncSetAttribute(score_kernel, cudaFuncAttributeMaxDynamicSharedMemorySize,
                         SMEM_TOTAL);

    cudaMemsetAsync(out, 0, (size_t)B_ * D_ * sizeof(float), 0);
    convert_values_kernel<<<8192, 256>>>(values);
    convert_w1_kernel<<<dim3(16, 16), 256>>>(W1w);
    pq_kernel<<<B_, 512>>>(query, W2w, W1b, W2b);
    score_kernel<<<2048, 256, SMEM_TOTAL>>>(Vw);
    softmax_kernel<<<B_, 256>>>(out);
    context_kernel<<<dim3(16, B_), 256>>>(values, out);
}

// round 10
// speedup vs baseline: 1.2524x; 1.2524x over previous
#include <cuda_runtime.h>
#include <cuda_fp16.h>
#include <math.h>
#include <stdint.h>

#define B_ 32
#define T_ 2048
#define D_ 512
#define U_ 512
#define MT 65536            // B_*T_

// ---- score GEMM tiling ----
#define TILE_M 128
#define TILE_N 128
#define KC 64               // K elems per pipeline chunk (128B fp16 rows, SW128)
#define NCHUNK 8            // 512/64
#define A_H 0               // A-hi plane: 128 rows x 128B = 16KB
#define A_L 16384           // A-lo plane: 16KB
#define B_H 32768           // B-hi plane: 16KB
#define STAGE 49152
#define SMEM_TOTAL (2*STAGE + 1024)   // 99328 B -> 2 CTAs/SM

// ---- scratch (device globals: allocation-free) ----
__device__ float g_score[MT];
__device__ float g_pq[B_ * U_];
__device__ __half g_vh[(size_t)MT * D_];
__device__ __half g_vl[(size_t)MT * D_];
__device__ __half g_w1h[U_ * D_];   // [n][k] transposed, K-major

// ---------------------------------------------------------------------------
// PTX helpers — baseline (non-"a") features only: mma.sync / ldmatrix / cp.async
// ---------------------------------------------------------------------------
__device__ __forceinline__ uint32_t smem_u32(const void* p) {
    uint32_t a;
    asm("{ .reg .u64 t; cvta.to.shared.u64 t, %1; cvt.u32.u64 %0, t; }" : "=r"(a) : "l"(p));
    return a;
}
#define SWZ(o) ((o) ^ (((o) >> 3) & 0x70))   // SW128 for 128B rows

__device__ __forceinline__ void cp16(uint32_t dst, const void* src) {
    asm volatile("cp.async.cg.shared.global [%0], [%1], 16;" :: "r"(dst), "l"(src));
}
__device__ __forceinline__ void ldm4(uint32_t* r, uint32_t addr) {
    asm volatile("ldmatrix.sync.aligned.m8n8.x4.shared.b16 {%0,%1,%2,%3}, [%4];"
                 : "=r"(r[0]), "=r"(r[1]), "=r"(r[2]), "=r"(r[3]) : "r"(addr));
}
__device__ __forceinline__ void mma_f16(float* d, const uint32_t* a,
                                        uint32_t b0, uint32_t b1) {
    asm volatile(
        "mma.sync.aligned.m16n8k16.row.col.f32.f16.f16.f32 "
        "{%0,%1,%2,%3}, {%4,%5,%6,%7}, {%8,%9}, {%0,%1,%2,%3};"
        : "+f"(d[0]), "+f"(d[1]), "+f"(d[2]), "+f"(d[3])
        : "r"(a[0]), "r"(a[1]), "r"(a[2]), "r"(a[3]), "r"(b0), "r"(b1));
}

// ---------------------------------------------------------------------------
// values fp32 -> fp16 hi + fp16 lo residual
// ---------------------------------------------------------------------------
__global__ void convert_values_kernel(const float* __restrict__ v) {
    const float4* v4 = (const float4*)v;
    __half2* vh2 = (__half2*)g_vh;
    __half2* vl2 = (__half2*)g_vl;
    size_t n4 = (size_t)MT * D_ / 4;
    for (size_t i = (size_t)blockIdx.x * blockDim.x + threadIdx.x; i < n4;
         i += (size_t)gridDim.x * blockDim.x) {
        float4 x = v4[i];
        __half hx = __float2half(x.x), hy = __float2half(x.y);
        __half hz = __float2half(x.z), hw = __float2half(x.w);
        __half2 h0, h1, l0, l1;
        h0.x = hx; h0.y = hy; h1.x = hz; h1.y = hw;
        l0.x = __float2half(x.x - __half2float(hx));
        l0.y = __float2half(x.y - __half2float(hy));
        l1.x = __float2half(x.z - __half2float(hz));
        l1.y = __float2half(x.w - __half2float(hw));
        vh2[2*i] = h0; vh2[2*i+1] = h1;
        vl2[2*i] = l0; vl2[2*i+1] = l1;
    }
}

// W1 [K][N] -> transposed fp16 [N][K]
__global__ void convert_w1_kernel(const float* __restrict__ W1) {
    __shared__ float t[32][33];
    int k0 = blockIdx.y * 32, n0 = blockIdx.x * 32;
    int tx = threadIdx.x & 31, ty = threadIdx.x >> 5;
    for (int r = ty; r < 32; r += 8) t[r][tx] = W1[(k0 + r) * U_ + n0 + tx];
    __syncthreads();
    for (int r = ty; r < 32; r += 8)
        g_w1h[(size_t)(n0 + r) * D_ + k0 + tx] = __float2half(t[tx][r]);
}

// ---------------------------------------------------------------------------
// proj_q + bias fold; also zeroes g_score (atomicAdd target)
// ---------------------------------------------------------------------------
__global__ void pq_kernel(const float* __restrict__ query,
                          const float* __restrict__ W2,
                          const float* __restrict__ W1b,
                          const float* __restrict__ W2b) {
    __shared__ float qs[D_];
    int b = blockIdx.x, u = threadIdx.x;
    qs[u] = query[b * D_ + u];
    for (int i = b * 512 + u; i < MT; i += B_ * 512) g_score[i] = 0.f;
    __syncthreads();
    float acc = 0.f;
#pragma unroll 8
    for (int d = 0; d < D_; d++) acc = fmaf(qs[d], W2[d * U_ + u], acc);
    g_pq[b * U_ + u] = acc + W1b[u] + W2b[u];
}

// ---------------------------------------------------------------------------
// Score GEMM via mma.sync fp16x2 (A split hi/lo, B hi) + fused tanh/Vw epilogue
// grid: 2048 = 512 m-tiles x 4 n-slices; 256 threads (8 warps, 64x32 each)
// 2 CTAs/SM; SW128-swizzled 128B rows, no padding
// ---------------------------------------------------------------------------
extern __shared__ char smem_raw[];

__global__ __launch_bounds__(256, 2)
void score_kernel(const float* __restrict__ Vw) {
    const int tid  = threadIdx.x;
    const int lane = tid & 31;
    const int mtile = blockIdx.x >> 2;
    const int nq    = blockIdx.x & 3;
    const int row0  = mtile * TILE_M;
    const int b     = row0 >> 11;          // T_=2048
    const int n0    = nq * TILE_N;
    const int wid   = tid >> 5;
    const int m_w   = (wid >> 2) * 64;
    const int n_w   = (wid & 3) * 32;

    uint32_t sb = smem_u32(smem_raw);
    float* pqs = (float*)(smem_raw + 2 * STAGE);
    float* vws = pqs + 128;
    if (tid < 128) {
        pqs[tid] = g_pq[b * U_ + n0 + tid];
        vws[tid] = Vw[n0 + tid];
    }

    // ldmatrix per-lane address components (XOR swizzle folded per-lane)
    const int rowA = lane & 15;
    const int colA = (lane >> 4) * 16;                   // 16B chunk within k16 step
    const uint32_t axor = (rowA & 7) * 16;
    const int rowB = (lane & 7) + ((lane >> 3) & 1) * 8;
    const int colB = (lane >> 4) * 16;
    const uint32_t bxor = (rowB & 7) * 16;

    float acc[4][4][4];
#pragma unroll
    for (int i = 0; i < 4; i++)
#pragma unroll
        for (int j = 0; j < 4; j++)
#pragma unroll
            for (int r = 0; r < 4; r++) acc[i][j][r] = 0.f;

    const __half* Agh = g_vh  + (size_t)row0 * D_;
    const __half* Agl = g_vl  + (size_t)row0 * D_;
    const __half* Bgh = g_w1h + (size_t)n0   * D_;

    // loader: each plane 1024 granules (16B); 256 thr x 4 iters
    // row = tid>>1 (0..127), chunk16 = (tid&1)*4 + i
    const int lrow = tid >> 1;
    const int lch0 = (tid & 1) * 4;

#define LOAD_CHUNK(c, s)                                                     \
    do {                                                                     \
        uint32_t st = sb + (s) * STAGE;                                      \
        int k0 = (c) * KC;                                                   \
        _Pragma("unroll")                                                    \
        for (int i = 0; i < 4; i++) {                                        \
            int c16 = lch0 + i;                                              \
            uint32_t doff = SWZ(lrow * 128 + c16 * 16);                      \
            size_t soff = (size_t)lrow * D_ + k0 + c16 * 8;                  \
            cp16(st + A_H + doff, Agh + soff);                               \
            cp16(st + A_L + doff, Agl + soff);                               \
            cp16(st + B_H + doff, Bgh + soff);                               \
        }                                                                    \
        asm volatile("cp.async.commit_group;" ::: "memory");                 \
    } while (0)

    LOAD_CHUNK(0, 0);

    // per-lane fragment bases (row part linear; col part XORed per k-step)
    const uint32_t aho = A_H + (m_w + rowA) * 128;
    const uint32_t alo = A_L + (m_w + rowA) * 128;
    const uint32_t bho = B_H + (n_w + rowB) * 128;

    for (int c = 0; c < NCHUNK; c++) {
        int s = c & 1;
        if (c + 1 < NCHUNK) {
            LOAD_CHUNK(c + 1, s ^ 1);
            asm volatile("cp.async.wait_group 1;" ::: "memory");
        } else {
            asm volatile("cp.async.wait_group 0;" ::: "memory");
        }
        __syncthreads();

        const uint32_t st = sb + s * STAGE;
#pragma unroll
        for (int k = 0; k < 4; k++) {                 // 4 x k16 per 64-chunk
            const uint32_t ka = (uint32_t)((k * 32 + colA) ^ axor);
            const uint32_t kb = (uint32_t)((k * 32 + colB) ^ bxor);

            // ---- pass 1: Ah * Bh ----
            uint32_t ah[4][4], bh[2][4];
#pragma unroll
            for (int i = 0; i < 4; i++)
                ldm4(ah[i], st + aho + i * 2048 + ka);
#pragma unroll
            for (int jj = 0; jj < 2; jj++)
                ldm4(bh[jj], st + bho + jj * 2048 + kb);
#pragma unroll
            for (int i = 0; i < 4; i++)
#pragma unroll
                for (int j = 0; j < 4; j++)
                    mma_f16(acc[i][j], ah[i],
                            bh[j >> 1][j & 1], bh[j >> 1][2 + (j & 1)]);

            // ---- pass 2: Al * Bh ----
            uint32_t al[4][4];
#pragma unroll
            for (int i = 0; i < 4; i++)
                ldm4(al[i], st + alo + i * 2048 + ka);
#pragma unroll
            for (int i = 0; i < 4; i++)
#pragma unroll
                for (int j = 0; j < 4; j++)
                    mma_f16(acc[i][j], al[i],
                            bh[j >> 1][j & 1], bh[j >> 1][2 + (j & 1)]);
        }
        __syncthreads();
    }

    // Epilogue: tanh(acc+pq)*Vw, reduce over n (regs -> shfl -> atomicAdd)
    float part[4][2];
#pragma unroll
    for (int i = 0; i < 4; i++) { part[i][0] = 0.f; part[i][1] = 0.f; }
#pragma unroll
    for (int i = 0; i < 4; i++)
#pragma unroll
        for (int j = 0; j < 4; j++)
#pragma unroll
            for (int r = 0; r < 4; r++) {
                int nl = n_w + j * 8 + 2 * (lane & 3) + (r & 1);
                float x = acc[i][j][r] + pqs[nl];
                part[i][r >> 1] += tanhf(x) * vws[nl];
            }
#pragma unroll
    for (int i = 0; i < 4; i++)
#pragma unroll
        for (int h = 0; h < 2; h++) {
            float v = part[i][h];
            v += __shfl_xor_sync(0xffffffffu, v, 1);
            v += __shfl_xor_sync(0xffffffffu, v, 2);
            if ((lane & 3) == 0)
                atomicAdd(&g_score[row0 + m_w + i * 16 + h * 8 + (lane >> 2)], v);
        }
}

// ---------------------------------------------------------------------------
// Softmax over T per batch; weights -> d_out[B*D ..)
// ---------------------------------------------------------------------------
__global__ void softmax_kernel(float* __restrict__ out) {
    __shared__ float sm[256];
    int b = blockIdx.x, tid = threadIdx.x;
    const float* sc = g_score + b * T_;
    float m = -1e30f;
    for (int t = tid; t < T_; t += 256) m = fmaxf(m, sc[t]);
    sm[tid] = m; __syncthreads();
    for (int s = 128; s > 0; s >>= 1) {
        if (tid < s) sm[tid] = fmaxf(sm[tid], sm[tid + s]);
        __syncthreads();
    }
    float mx = sm[0]; __syncthreads();
    float sum = 0.f;
    for (int t = tid; t < T_; t += 256) sum += __expf(sc[t] - mx);
    sm[tid] = sum; __syncthreads();
    for (int s = 128; s > 0; s >>= 1) {
        if (tid < s) sm[tid] += sm[tid + s];
        __syncthreads();
    }
    float inv = 1.f / sm[0];
    float* w = out + B_ * D_ + b * T_;
    for (int t = tid; t < T_; t += 256) w[t] = __expf(sc[t] - mx) * inv;
}

// ---------------------------------------------------------------------------
// context[b,d] = sum_t w[b,t] * values[b,t,d]
// ---------------------------------------------------------------------------
__global__ void context_kernel(const float* __restrict__ values,
                               float* __restrict__ out) {
    int b = blockIdx.y;
    int t0 = blockIdx.x * 128;
    int d4 = threadIdx.x & 127;
    int th = threadIdx.x >> 7;
    const float* w = out + B_ * D_ + b * T_ + t0;
    const float4* v = (const float4*)(values + ((size_t)b * T_ + t0) * D_) + d4;
    float4 acc = make_float4(0.f, 0.f, 0.f, 0.f);
#pragma unroll 8
    for (int t = th; t < 128; t += 2) {
        float wt = w[t];
        float4 x = v[(size_t)t * 128];
        acc.x = fmaf(wt, x.x, acc.x);
        acc.y = fmaf(wt, x.y, acc.y);
        acc.z = fmaf(wt, x.z, acc.z);
        acc.w = fmaf(wt, x.w, acc.w);
    }
    float* o = out + b * D_ + d4 * 4;
    atomicAdd(o + 0, acc.x);
    atomicAdd(o + 1, acc.y);
    atomicAdd(o + 2, acc.z);
    atomicAdd(o + 3, acc.w);
}

// ---------------------------------------------------------------------------
extern "C" void kernel_launch(void* const* d_in, const int* in_sizes, int n_in,
                              void* d_out, int out_size) {
    const float* values = (const float*)d_in[0];
    const float* query  = (const float*)d_in[1];
    const float* W1w    = (const float*)d_in[2];
    const float* W1b    = (const float*)d_in[3];
    const float* W2w    = (const float*)d_in[4];
    const float* W2b    = (const float*)d_in[5];
    const float* Vw     = (const float*)d_in[6];
    // d_in[7] (V_b) unused: softmax is shift-invariant.
    float* out = (float*)d_out;

    cudaFuncSetAttribute(score_kernel, cudaFuncAttributeMaxDynamicSharedMemorySize,
                         SMEM_TOTAL);

    cudaMemsetAsync(out, 0, (size_t)B_ * D_ * sizeof(float), 0);
    convert_values_kernel<<<8192, 256>>>(values);
    convert_w1_kernel<<<dim3(16, 16), 256>>>(W1w);
    pq_kernel<<<B_, 512>>>(query, W2w, W1b, W2b);
    score_kernel<<<2048, 256, SMEM_TOTAL>>>(Vw);
    softmax_kernel<<<B_, 256>>>(out);
    context_kernel<<<dim3(16, B_), 256>>>(values, out);
}

// round 11
// speedup vs baseline: 1.7481x; 1.3957x over previous
#include <cuda_runtime.h>
#include <cuda_fp16.h>
#include <math.h>
#include <stdint.h>

#define B_ 32
#define T_ 2048
#define D_ 512
#define U_ 512
#define MT 65536            // B_*T_

// ---- score GEMM tiling ----
#define TILE_M 128
#define TILE_N 128
#define KC 64               // K elems per pipeline chunk (128B fp16 rows, SW128)
#define NCHUNK 8            // 512/64
#define A_H 0               // A plane: 128 rows x 128B = 16KB
#define B_H 16384           // B plane: 16KB
#define STAGE 32768
#define SMEM_TOTAL (2*STAGE + 1024)   // 66560 B -> 2 CTAs/SM

// ---- scratch (device globals: allocation-free) ----
__device__ float g_score[MT];
__device__ float g_pq[B_ * U_];
__device__ __half g_vh[(size_t)MT * D_];
__device__ __half g_w1h[U_ * D_];   // [n][k] transposed, K-major

// ---------------------------------------------------------------------------
// PTX helpers — baseline (non-"a") features only: mma.sync / ldmatrix / cp.async
// ---------------------------------------------------------------------------
__device__ __forceinline__ uint32_t smem_u32(const void* p) {
    uint32_t a;
    asm("{ .reg .u64 t; cvta.to.shared.u64 t, %1; cvt.u32.u64 %0, t; }" : "=r"(a) : "l"(p));
    return a;
}
#define SWZ(o) ((o) ^ (((o) >> 3) & 0x70))   // SW128 for 128B rows

__device__ __forceinline__ void cp16(uint32_t dst, const void* src) {
    asm volatile("cp.async.cg.shared.global [%0], [%1], 16;" :: "r"(dst), "l"(src));
}
__device__ __forceinline__ void ldm4(uint32_t* r, uint32_t addr) {
    asm volatile("ldmatrix.sync.aligned.m8n8.x4.shared.b16 {%0,%1,%2,%3}, [%4];"
                 : "=r"(r[0]), "=r"(r[1]), "=r"(r[2]), "=r"(r[3]) : "r"(addr));
}
__device__ __forceinline__ void mma_f16(float* d, const uint32_t* a,
                                        uint32_t b0, uint32_t b1) {
    asm volatile(
        "mma.sync.aligned.m16n8k16.row.col.f32.f16.f16.f32 "
        "{%0,%1,%2,%3}, {%4,%5,%6,%7}, {%8,%9}, {%0,%1,%2,%3};"
        : "+f"(d[0]), "+f"(d[1]), "+f"(d[2]), "+f"(d[3])
        : "r"(a[0]), "r"(a[1]), "r"(a[2]), "r"(a[3]), "r"(b0), "r"(b1));
}

// ---------------------------------------------------------------------------
// values fp32 -> fp16 (single hi plane)
// ---------------------------------------------------------------------------
__global__ void convert_values_kernel(const float* __restrict__ v) {
    const float4* v4 = (const float4*)v;
    __half2* vh2 = (__half2*)g_vh;
    size_t n4 = (size_t)MT * D_ / 4;
    for (size_t i = (size_t)blockIdx.x * blockDim.x + threadIdx.x; i < n4;
         i += (size_t)gridDim.x * blockDim.x) {
        float4 x = v4[i];
        __half2 h0, h1;
        h0.x = __float2half(x.x); h0.y = __float2half(x.y);
        h1.x = __float2half(x.z); h1.y = __float2half(x.w);
        vh2[2*i] = h0; vh2[2*i+1] = h1;
    }
}

// W1 [K][N] -> transposed fp16 [N][K]
__global__ void convert_w1_kernel(const float* __restrict__ W1) {
    __shared__ float t[32][33];
    int k0 = blockIdx.y * 32, n0 = blockIdx.x * 32;
    int tx = threadIdx.x & 31, ty = threadIdx.x >> 5;
    for (int r = ty; r < 32; r += 8) t[r][tx] = W1[(k0 + r) * U_ + n0 + tx];
    __syncthreads();
    for (int r = ty; r < 32; r += 8)
        g_w1h[(size_t)(n0 + r) * D_ + k0 + tx] = __float2half(t[tx][r]);
}

// ---------------------------------------------------------------------------
// proj_q + bias fold; also zeroes g_score (atomicAdd target)
// ---------------------------------------------------------------------------
__global__ void pq_kernel(const float* __restrict__ query,
                          const float* __restrict__ W2,
                          const float* __restrict__ W1b,
                          const float* __restrict__ W2b) {
    __shared__ float qs[D_];
    int b = blockIdx.x, u = threadIdx.x;
    qs[u] = query[b * D_ + u];
    for (int i = b * 512 + u; i < MT; i += B_ * 512) g_score[i] = 0.f;
    __syncthreads();
    float acc = 0.f;
#pragma unroll 8
    for (int d = 0; d < D_; d++) acc = fmaf(qs[d], W2[d * U_ + u], acc);
    g_pq[b * U_ + u] = acc + W1b[u] + W2b[u];
}

// ---------------------------------------------------------------------------
// Score GEMM via single fp16 mma.sync + fused tanh/Vw epilogue
// grid: 2048 = 512 m-tiles x 4 n-slices; 256 threads (8 warps, 64x32 each)
// 2 CTAs/SM; SW128-swizzled 128B rows, no padding
// ---------------------------------------------------------------------------
extern __shared__ char smem_raw[];

__global__ __launch_bounds__(256, 2)
void score_kernel(const float* __restrict__ Vw) {
    const int tid  = threadIdx.x;
    const int lane = tid & 31;
    const int mtile = blockIdx.x >> 2;
    const int nq    = blockIdx.x & 3;
    const int row0  = mtile * TILE_M;
    const int b     = row0 >> 11;          // T_=2048
    const int n0    = nq * TILE_N;
    const int wid   = tid >> 5;
    const int m_w   = (wid >> 2) * 64;
    const int n_w   = (wid & 3) * 32;

    uint32_t sb = smem_u32(smem_raw);
    float* pqs = (float*)(smem_raw + 2 * STAGE);
    float* vws = pqs + 128;
    if (tid < 128) {
        pqs[tid] = g_pq[b * U_ + n0 + tid];
        vws[tid] = Vw[n0 + tid];
    }

    // ldmatrix per-lane address components (XOR swizzle folded per-lane)
    const int rowA = lane & 15;
    const int colA = (lane >> 4) * 16;                   // 16B chunk within k16 step
    const uint32_t axor = (rowA & 7) * 16;
    const int rowB = (lane & 7) + ((lane >> 3) & 1) * 8;
    const int colB = (lane >> 4) * 16;
    const uint32_t bxor = (rowB & 7) * 16;

    float acc[4][4][4];
#pragma unroll
    for (int i = 0; i < 4; i++)
#pragma unroll
        for (int j = 0; j < 4; j++)
#pragma unroll
            for (int r = 0; r < 4; r++) acc[i][j][r] = 0.f;

    const __half* Agh = g_vh  + (size_t)row0 * D_;
    const __half* Bgh = g_w1h + (size_t)n0   * D_;

    // loader: each plane 1024 granules (16B); 256 thr x 4 iters per plane
    const int lrow = tid >> 1;
    const int lch0 = (tid & 1) * 4;

#define LOAD_CHUNK(c, s)                                                     \
    do {                                                                     \
        uint32_t st = sb + (s) * STAGE;                                      \
        int k0 = (c) * KC;                                                   \
        _Pragma("unroll")                                                    \
        for (int i = 0; i < 4; i++) {                                        \
            int c16 = lch0 + i;                                              \
            uint32_t doff = SWZ(lrow * 128 + c16 * 16);                      \
            size_t soff = (size_t)lrow * D_ + k0 + c16 * 8;                  \
            cp16(st + A_H + doff, Agh + soff);                               \
            cp16(st + B_H + doff, Bgh + soff);                               \
        }                                                                    \
        asm volatile("cp.async.commit_group;" ::: "memory");                 \
    } while (0)

    LOAD_CHUNK(0, 0);

    // per-lane fragment bases (row part linear; col part XORed per k-step)
    const uint32_t aho = A_H + (m_w + rowA) * 128;
    const uint32_t bho = B_H + (n_w + rowB) * 128;

    for (int c = 0; c < NCHUNK; c++) {
        int s = c & 1;
        if (c + 1 < NCHUNK) {
            LOAD_CHUNK(c + 1, s ^ 1);
            asm volatile("cp.async.wait_group 1;" ::: "memory");
        } else {
            asm volatile("cp.async.wait_group 0;" ::: "memory");
        }
        __syncthreads();

        const uint32_t st = sb + s * STAGE;
#pragma unroll
        for (int k = 0; k < 4; k++) {                 // 4 x k16 per 64-chunk
            const uint32_t ka = (uint32_t)((k * 32 + colA) ^ axor);
            const uint32_t kb = (uint32_t)((k * 32 + colB) ^ bxor);

            uint32_t ah[4][4], bh[2][4];
#pragma unroll
            for (int i = 0; i < 4; i++)
                ldm4(ah[i], st + aho + i * 2048 + ka);
#pragma unroll
            for (int jj = 0; jj < 2; jj++)
                ldm4(bh[jj], st + bho + jj * 2048 + kb);
#pragma unroll
            for (int i = 0; i < 4; i++)
#pragma unroll
                for (int j = 0; j < 4; j++)
                    mma_f16(acc[i][j], ah[i],
                            bh[j >> 1][j & 1], bh[j >> 1][2 + (j & 1)]);
        }
        __syncthreads();
    }

    // Epilogue: tanh(acc+pq)*Vw, reduce over n (regs -> shfl -> atomicAdd)
    float part[4][2];
#pragma unroll
    for (int i = 0; i < 4; i++) { part[i][0] = 0.f; part[i][1] = 0.f; }
#pragma unroll
    for (int i = 0; i < 4; i++)
#pragma unroll
        for (int j = 0; j < 4; j++)
#pragma unroll
            for (int r = 0; r < 4; r++) {
                int nl = n_w + j * 8 + 2 * (lane & 3) + (r & 1);
                float x = acc[i][j][r] + pqs[nl];
                part[i][r >> 1] += tanhf(x) * vws[nl];
            }
#pragma unroll
    for (int i = 0; i < 4; i++)
#pragma unroll
        for (int h = 0; h < 2; h++) {
            float v = part[i][h];
            v += __shfl_xor_sync(0xffffffffu, v, 1);
            v += __shfl_xor_sync(0xffffffffu, v, 2);
            if ((lane & 3) == 0)
                atomicAdd(&g_score[row0 + m_w + i * 16 + h * 8 + (lane >> 2)], v);
        }
}

// ---------------------------------------------------------------------------
// Softmax over T per batch; weights -> d_out[B*D ..)
// ---------------------------------------------------------------------------
__global__ void softmax_kernel(float* __restrict__ out) {
    __shared__ float sm[256];
    int b = blockIdx.x, tid = threadIdx.x;
    const float* sc = g_score + b * T_;
    float m = -1e30f;
    for (int t = tid; t < T_; t += 256) m = fmaxf(m, sc[t]);
    sm[tid] = m; __syncthreads();
    for (int s = 128; s > 0; s >>= 1) {
        if (tid < s) sm[tid] = fmaxf(sm[tid], sm[tid + s]);
        __syncthreads();
    }
    float mx = sm[0]; __syncthreads();
    float sum = 0.f;
    for (int t = tid; t < T_; t += 256) sum += __expf(sc[t] - mx);
    sm[tid] = sum; __syncthreads();
    for (int s = 128; s > 0; s >>= 1) {
        if (tid < s) sm[tid] += sm[tid + s];
        __syncthreads();
    }
    float inv = 1.f / sm[0];
    float* w = out + B_ * D_ + b * T_;
    for (int t = tid; t < T_; t += 256) w[t] = __expf(sc[t] - mx) * inv;
}

// ---------------------------------------------------------------------------
// context[b,d] = sum_t w[b,t] * values[b,t,d]
// ---------------------------------------------------------------------------
__global__ void context_kernel(const float* __restrict__ values,
                               float* __restrict__ out) {
    int b = blockIdx.y;
    int t0 = blockIdx.x * 128;
    int d4 = threadIdx.x & 127;
    int th = threadIdx.x >> 7;
    const float* w = out + B_ * D_ + b * T_ + t0;
    const float4* v = (const float4*)(values + ((size_t)b * T_ + t0) * D_) + d4;
    float4 acc = make_float4(0.f, 0.f, 0.f, 0.f);
#pragma unroll 8
    for (int t = th; t < 128; t += 2) {
        float wt = w[t];
        float4 x = v[(size_t)t * 128];
        acc.x = fmaf(wt, x.x, acc.x);
        acc.y = fmaf(wt, x.y, acc.y);
        acc.z = fmaf(wt, x.z, acc.z);
        acc.w = fmaf(wt, x.w, acc.w);
    }
    float* o = out + b * D_ + d4 * 4;
    atomicAdd(o + 0, acc.x);
    atomicAdd(o + 1, acc.y);
    atomicAdd(o + 2, acc.z);
    atomicAdd(o + 3, acc.w);
}

// ---------------------------------------------------------------------------
extern "C" void kernel_launch(void* const* d_in, const int* in_sizes, int n_in,
                              void* d_out, int out_size) {
    const float* values = (const float*)d_in[0];
    const float* query  = (const float*)d_in[1];
    const float* W1w    = (const float*)d_in[2];
    const float* W1b    = (const float*)d_in[3];
    const float* W2w    = (const float*)d_in[4];
    const float* W2b    = (const float*)d_in[5];
    const float* Vw     = (const float*)d_in[6];
    // d_in[7] (V_b) unused: softmax is shift-invariant.
    float* out = (float*)d_out;

    cudaFuncSetAttribute(score_kernel, cudaFuncAttributeMaxDynamicSharedMemorySize,
                         SMEM_TOTAL);

    cudaMemsetAsync(out, 0, (size_t)B_ * D_ * sizeof(float), 0);
    convert_values_kernel<<<8192, 256>>>(values);
    convert_w1_kernel<<<dim3(16, 16), 256>>>(W1w);
    pq_kernel<<<B_, 512>>>(query, W2w, W1b, W2b);
    score_kernel<<<2048, 256, SMEM_TOTAL>>>(Vw);
    softmax_kernel<<<B_, 256>>>(out);
    context_kernel<<<dim3(16, B_), 256>>>(values, out);
}